// round 11
// baseline (speedup 1.0000x reference)
#include <cuda_runtime.h>
#include <math.h>

#define NPTS 16384
#define NCELL 24
#define NCELL2 576
#define NCELL3 13824
#define INV_CELL 0.1875f            // NCELL / 128
#define CELLSZ 5.3333333f           // 128 / NCELL
#define CAP 8                       // slots per cell
#define OVF_CAP 256
#define QBLK 256                    // 8 warps per block
#define WPB 8
#define NQBLK (2 * NCELL3 / WPB)    // 3456 query blocks

__device__ int    g_ccnt[2][NCELL3];
__device__ float4 g_slots[2][NCELL3 * CAP];   // w = -0.5*||p||^2
__device__ int    g_ovfn[2];
__device__ float4 g_ovf[2][OVF_CAP];
__device__ float  g_acc;
__device__ int    g_done;

// ---- build: bin points into fixed-capacity cells ----
__global__ void build_kernel(const float* __restrict__ A,
                             const float* __restrict__ B) {
    int i = blockIdx.x * blockDim.x + threadIdx.x;   // 0 .. 2*NPTS-1
    int set = i >> 14;
    int idx = i & (NPTS - 1);
    const float* __restrict__ P = set ? B : A;
    float x = P[3 * idx], y = P[3 * idx + 1], z = P[3 * idx + 2];
    int cx = min((int)(x * INV_CELL), NCELL - 1);
    int cy = min((int)(y * INV_CELL), NCELL - 1);
    int cz = min((int)(z * INV_CELL), NCELL - 1);
    int c = (cx * NCELL + cy) * NCELL + cz;
    float4 pt = make_float4(x, y, z, -0.5f * (x * x + y * y + z * z));
    int pos = atomicAdd(&g_ccnt[set][c], 1);
    if (pos < CAP) {
        g_slots[set][c * CAP + pos] = pt;
    } else {
        int o = atomicAdd(&g_ovfn[set], 1);
        if (o < OVF_CAP) g_ovf[set][o] = pt;
    }
}

// Warp-collective NN for one (warp-uniform) query point. Returns d2 (all lanes).
__device__ __forceinline__ float warp_nn(float4 q, int lane,
                                         const int* __restrict__ ccnt,
                                         const float4* __restrict__ slots,
                                         const float4* __restrict__ ovf,
                                         int novf) {
    int qx = min((int)(q.x * INV_CELL), NCELL - 1);
    int qy = min((int)(q.y * INV_CELL), NCELL - 1);
    int qz = min((int)(q.z * INV_CELL), NCELL - 1);

    float best = -1e30f;   // max over refs of e = q.r - 0.5*||r||^2

    // radius-1: 27 cells, one per lane (lanes 27-31 idle)
    if (lane < 27) {
        int ix = qx + lane / 9 - 1;
        int iy = qy + (lane % 9) / 3 - 1;
        int iz = qz + lane % 3 - 1;
        if (ix >= 0 && ix < NCELL && iy >= 0 && iy < NCELL &&
            iz >= 0 && iz < NCELL) {
            int c = (ix * NCELL + iy) * NCELL + iz;
            int n = min(ccnt[c], CAP);
            const float4* s = slots + c * CAP;
            for (int j = 0; j < n; j++) {
                float4 t = s[j];
                float e = fmaf(q.x, t.x, fmaf(q.y, t.y, fmaf(q.z, t.z, t.w)));
                best = fmaxf(best, e);
            }
        }
    }
    // overflow refs (expected 0)
    for (int o = lane; o < novf; o += 32) {
        float4 t = ovf[o];
        float e = fmaf(q.x, t.x, fmaf(q.y, t.y, fmaf(q.z, t.z, t.w)));
        best = fmaxf(best, e);
    }
    #pragma unroll
    for (int o = 16; o > 0; o >>= 1)
        best = fmaxf(best, __shfl_xor_sync(0xFFFFFFFFu, best, o));
    float d2 = -2.0f * (q.w + best);

    // rare expansion (~0.7% of queries), warp-uniform
    for (int r = 2; r <= NCELL; r++) {
        float rb = (r - 1) * CELLSZ;
        if (d2 <= rb * rb) break;
        int x0 = max(qx - r, 0), x1 = min(qx + r, NCELL - 1);
        int y0 = max(qy - r, 0), y1 = min(qy + r, NCELL - 1);
        int z0 = max(qz - r, 0), z1 = min(qz + r, NCELL - 1);
        int k = 0;
        for (int ix = x0; ix <= x1; ix++)
            for (int iy = y0; iy <= y1; iy++)
                for (int iz = z0; iz <= z1; iz++) {
                    if ((k++ & 31) == lane) {
                        int c = (ix * NCELL + iy) * NCELL + iz;
                        int n = min(ccnt[c], CAP);
                        const float4* s = slots + c * CAP;
                        for (int j = 0; j < n; j++) {
                            float4 t = s[j];
                            float e = fmaf(q.x, t.x,
                                      fmaf(q.y, t.y, fmaf(q.z, t.z, t.w)));
                            best = fmaxf(best, e);
                        }
                    }
                }
        #pragma unroll
        for (int o = 16; o > 0; o >>= 1)
            best = fmaxf(best, __shfl_xor_sync(0xFFFFFFFFu, best, o));
        d2 = -2.0f * (q.w + best);
    }
    return d2;
}

// ---- query: one warp per (set, cell). Adjacent warps = adjacent cells. ----
__global__ __launch_bounds__(QBLK) void query_kernel(float* __restrict__ out) {
    __shared__ float red[WPB];
    int warp = threadIdx.x >> 5;
    int lane = threadIdx.x & 31;
    int w = blockIdx.x * WPB + warp;        // 0 .. 2*NCELL3-1
    int set = (w >= NCELL3);
    int cell = set ? (w - NCELL3) : w;
    int rs = set ^ 1;

    const int* __restrict__ ccnt = g_ccnt[rs];
    const float4* __restrict__ slots = g_slots[rs];
    const float4* __restrict__ ovf = g_ovf[rs];
    int novf = min(g_ovfn[rs], OVF_CAP);

    float local = 0.0f;

    int nq = min(g_ccnt[set][cell], CAP);
    for (int j = 0; j < nq; j++) {
        float4 q = g_slots[set][cell * CAP + j];   // broadcast load
        float d2 = warp_nn(q, lane, ccnt, slots, ovf, novf);
        if (lane == 0) local += sqrtf(fmaxf(d2, 0.0f));
    }

    // warps 0 and 1 also run the (expected-empty) overflow lists as queries
    if (w < 2) {
        int myset = w;
        int myrs = myset ^ 1;
        int no = min(g_ovfn[myset], OVF_CAP);
        int nro = min(g_ovfn[myrs], OVF_CAP);
        for (int o = 0; o < no; o++) {
            float4 q = g_ovf[myset][o];
            float d2 = warp_nn(q, lane, g_ccnt[myrs], g_slots[myrs],
                               g_ovf[myrs], nro);
            if (lane == 0) local += sqrtf(fmaxf(d2, 0.0f));
        }
    }

    if (lane == 0) red[warp] = local;
    __syncthreads();
    if (threadIdx.x == 0) {
        float bs = 0.0f;
        #pragma unroll
        for (int u = 0; u < WPB; u++) bs += red[u];
        atomicAdd(&g_acc, bs);
        __threadfence();
        int t = atomicAdd(&g_done, 1);
        if (t == NQBLK - 1) {
            out[0] = *((volatile float*)&g_acc) * (1.0f / (2.0f * NPTS));
            g_acc = 0.0f;
            g_done = 0;
            g_ovfn[0] = 0;
            g_ovfn[1] = 0;
        }
    }
    __syncthreads();
    // Last block (detected via shared flag from thread 0) resets cell counts.
    __shared__ int s_islast;
    if (threadIdx.x == 0)
        s_islast = 0;
    __syncthreads();
    // thread 0 learned whether it was last via t; rebroadcast:
    // (redo the check with a second flag write from the same thread)
    if (threadIdx.x == 0) {
        // g_done was reset to 0 by the last block only; safe detection:
        // re-use: we stored nothing — instead recompute via a second counter-free
        // method: thread 0 kept 't' in a register; propagate through shared.
        // NOTE: t is in scope only above; replicate by storing in red[0] earlier.
    }
    // --- simpler correct scheme: thread 0 wrote whether it was last into red ---
}

// The in-kernel reset above got convoluted; use a clean dedicated version:
__global__ __launch_bounds__(QBLK) void query_kernel2(float* __restrict__ out) {
    __shared__ float red[WPB];
    __shared__ int s_last;
    int warp = threadIdx.x >> 5;
    int lane = threadIdx.x & 31;
    int w = blockIdx.x * WPB + warp;
    int set = (w >= NCELL3);
    int cell = set ? (w - NCELL3) : w;
    int rs = set ^ 1;

    const int* __restrict__ ccnt = g_ccnt[rs];
    const float4* __restrict__ slots = g_slots[rs];
    const float4* __restrict__ ovf = g_ovf[rs];
    int novf = min(g_ovfn[rs], OVF_CAP);

    float local = 0.0f;
    int nq = min(g_ccnt[set][cell], CAP);
    for (int j = 0; j < nq; j++) {
        float4 q = g_slots[set][cell * CAP + j];
        float d2 = warp_nn(q, lane, ccnt, slots, ovf, novf);
        if (lane == 0) local += sqrtf(fmaxf(d2, 0.0f));
    }
    if (w < 2) {
        int myset = w, myrs = w ^ 1;
        int no = min(g_ovfn[myset], OVF_CAP);
        int nro = min(g_ovfn[myrs], OVF_CAP);
        for (int o = 0; o < no; o++) {
            float4 q = g_ovf[myset][o];
            float d2 = warp_nn(q, lane, g_ccnt[myrs], g_slots[myrs],
                               g_ovf[myrs], nro);
            if (lane == 0) local += sqrtf(fmaxf(d2, 0.0f));
        }
    }

    if (lane == 0) red[warp] = local;
    __syncthreads();
    if (threadIdx.x == 0) {
        float bs = 0.0f;
        #pragma unroll
        for (int u = 0; u < WPB; u++) bs += red[u];
        atomicAdd(&g_acc, bs);
        __threadfence();
        s_last = (atomicAdd(&g_done, 1) == NQBLK - 1);
    }
    __syncthreads();
    if (s_last) {
        // all other blocks have finished: write output and reset everything
        if (threadIdx.x == 0) {
            out[0] = *((volatile float*)&g_acc) * (1.0f / (2.0f * NPTS));
            g_acc = 0.0f;
            g_done = 0;
            g_ovfn[0] = 0;
            g_ovfn[1] = 0;
        }
        for (int c = threadIdx.x; c < 2 * NCELL3; c += QBLK)
            ((int*)g_ccnt)[c] = 0;
    }
}

extern "C" void kernel_launch(void* const* d_in, const int* in_sizes, int n_in,
                              void* d_out, int out_size) {
    const float* a = (const float*)d_in[0];
    const float* b = (const float*)d_in[1];
    float* out = (float*)d_out;

    build_kernel<<<(2 * NPTS) / 256, 256>>>(a, b);
    query_kernel2<<<NQBLK, QBLK>>>(out);
}

// round 12
// speedup vs baseline: 1.2835x; 1.2835x over previous
#include <cuda_runtime.h>
#include <math.h>

#define NPTS 16384
#define NCELL 24
#define NCELL3 13824
#define TWOC3 27648                 // 2 * NCELL3
#define INV_CELL 0.1875f            // NCELL / 128
#define CELLSZ 5.3333333f           // 128 / NCELL
#define CAP 6                       // slots per cell (expected overflow ~4 pts/set)
#define OVF_CAP 256
#define QBLK 128
#define NBM ((2 * NCELL3 * CAP) / QBLK)   // 1296 main query blocks
#define NQBLK (NBM + 2)                   // + 2 overflow-query blocks

__device__ int    g_ccnt[2][NCELL3];          // raw counts (may exceed CAP)
__device__ float4 g_slots[2][NCELL3 * CAP];   // w = -0.5*||p||^2
__device__ int    g_ovfn[2];
__device__ float4 g_ovf[2][OVF_CAP];
__device__ float  g_acc;
__device__ int    g_done;

// ---- build: bin points into fixed-capacity cells ----
__global__ void build_kernel(const float* __restrict__ A,
                             const float* __restrict__ B) {
    int i = blockIdx.x * blockDim.x + threadIdx.x;   // 0 .. 2*NPTS-1
    int set = i >> 14;
    int idx = i & (NPTS - 1);
    const float* __restrict__ P = set ? B : A;
    float x = P[3 * idx], y = P[3 * idx + 1], z = P[3 * idx + 2];
    int cx = min((int)(x * INV_CELL), NCELL - 1);
    int cy = min((int)(y * INV_CELL), NCELL - 1);
    int cz = min((int)(z * INV_CELL), NCELL - 1);
    int c = (cx * NCELL + cy) * NCELL + cz;
    float4 pt = make_float4(x, y, z, -0.5f * (x * x + y * y + z * z));
    int pos = atomicAdd(&g_ccnt[set][c], 1);
    if (pos < CAP) {
        g_slots[set][c * CAP + pos] = pt;
    } else {
        int o = atomicAdd(&g_ovfn[set], 1);
        if (o < OVF_CAP) g_ovf[set][o] = pt;
    }
}

// Per-thread dynamic box scan at radius r (used only on rare paths).
__device__ __forceinline__ float scan_box(float4 q, int qx, int qy, int qz,
                                          int r, const int* __restrict__ ccnt,
                                          const float4* __restrict__ slots,
                                          float best) {
    int x0 = max(qx - r, 0), x1 = min(qx + r, NCELL - 1);
    int y0 = max(qy - r, 0), y1 = min(qy + r, NCELL - 1);
    int z0 = max(qz - r, 0), z1 = min(qz + r, NCELL - 1);
    for (int ix = x0; ix <= x1; ix++)
        for (int iy = y0; iy <= y1; iy++)
            for (int iz = z0; iz <= z1; iz++) {
                int c = (ix * NCELL + iy) * NCELL + iz;
                int n = min(ccnt[c], CAP);
                const float4* s = slots + c * CAP;
                for (int jj = 0; jj < n; jj++) {
                    float4 t = s[jj];
                    float e = fmaf(q.x, t.x, fmaf(q.y, t.y, fmaf(q.z, t.z, t.w)));
                    best = fmaxf(best, e);
                }
            }
    return best;
}

// Full per-thread NN (rare paths: expansion from radius startr, overflow queries).
__device__ __forceinline__ float nn_finish(float4 q, int qx, int qy, int qz,
                                           int rs, float best, int startr) {
    const int* __restrict__ ccnt = g_ccnt[rs];
    const float4* __restrict__ slots = g_slots[rs];
    float d2 = -2.0f * (q.w + best);
    for (int r = startr; r <= NCELL; r++) {
        float rb = (r - 1) * CELLSZ;
        if (d2 <= rb * rb && r > startr) break;
        if (d2 <= rb * rb) break;
        best = scan_box(q, qx, qy, qz, r, ccnt, slots, best);
        d2 = -2.0f * (q.w + best);
    }
    return d2;
}

// ---- query: thread per (slot level j, set, cell); static branch-free r=1 scan ----
__global__ __launch_bounds__(QBLK) void query_kernel(float* __restrict__ out) {
    __shared__ float red[QBLK / 32];
    __shared__ int s_last;
    int bid = blockIdx.x;
    int tid = threadIdx.x;
    float v = 0.0f;

    if (bid < NBM) {
        int t = bid * QBLK + tid;
        int j = t / TWOC3;               // slot level 0..CAP-1
        int u = t - j * TWOC3;
        int set = (u >= NCELL3);
        int cell = u - set * NCELL3;
        int nq = min(g_ccnt[set][cell], CAP);
        if (j < nq) {
            int rs = set ^ 1;
            float4 q = g_slots[set][cell * CAP + j];
            int qx = cell / (NCELL * NCELL);
            int qy = (cell / NCELL) % NCELL;
            int qz = cell % NCELL;

            const int* __restrict__ ccnt = g_ccnt[rs];
            const float4* __restrict__ slots = g_slots[rs];
            float best = -1e30f;

            // 3x3x3 clamped neighborhood, fully static & predicated
            #pragma unroll
            for (int dx = -1; dx <= 1; dx++) {
                int ix = min(max(qx + dx, 0), NCELL - 1);
                #pragma unroll
                for (int dy = -1; dy <= 1; dy++) {
                    int iy = min(max(qy + dy, 0), NCELL - 1);
                    int cb = (ix * NCELL + iy) * NCELL;
                    #pragma unroll
                    for (int dz = -1; dz <= 1; dz++) {
                        int iz = min(max(qz + dz, 0), NCELL - 1);
                        int c = cb + iz;
                        int n = min(ccnt[c], CAP);
                        const float4* s = slots + c * CAP;
                        #pragma unroll
                        for (int jj = 0; jj < CAP; jj++) {
                            float4 p = s[jj];
                            float e = fmaf(q.x, p.x,
                                      fmaf(q.y, p.y, fmaf(q.z, p.z, p.w)));
                            best = (jj < n) ? fmaxf(best, e) : best;
                        }
                    }
                }
            }

            // overflow refs (warp-uniform count, expected ~0-4)
            int novf = min(g_ovfn[rs], OVF_CAP);
            for (int o = 0; o < novf; o++) {
                float4 p = g_ovf[rs][o];
                float e = fmaf(q.x, p.x, fmaf(q.y, p.y, fmaf(q.z, p.z, p.w)));
                best = fmaxf(best, e);
            }

            float d2 = -2.0f * (q.w + best);
            if (d2 > CELLSZ * CELLSZ)            // rare (~0.7%): expand
                d2 = nn_finish(q, qx, qy, qz, rs, best, 2);
            v = sqrtf(fmaxf(d2, 0.0f));
        }
    } else {
        // overflow points as queries (expected empty)
        int set = bid - NBM;
        int rs = set ^ 1;
        int no = min(g_ovfn[set], OVF_CAP);
        if (tid < no) {
            float4 q = g_ovf[set][tid];
            int qx = min((int)(q.x * INV_CELL), NCELL - 1);
            int qy = min((int)(q.y * INV_CELL), NCELL - 1);
            int qz = min((int)(q.z * INV_CELL), NCELL - 1);
            float best = -1e30f;
            // scan radius-1 box + own-overflow refs, then expand as needed
            best = scan_box(q, qx, qy, qz, 1, g_ccnt[rs], g_slots[rs], best);
            int novf = min(g_ovfn[rs], OVF_CAP);
            for (int o = 0; o < novf; o++) {
                float4 p = g_ovf[rs][o];
                float e = fmaf(q.x, p.x, fmaf(q.y, p.y, fmaf(q.z, p.z, p.w)));
                best = fmaxf(best, e);
            }
            float d2 = nn_finish(q, qx, qy, qz, rs, best, 2);
            v = sqrtf(fmaxf(d2, 0.0f));
        }
    }

    // ---- block sum -> global atomic; last block writes out + resets ----
    #pragma unroll
    for (int o = 16; o > 0; o >>= 1) v += __shfl_down_sync(0xFFFFFFFFu, v, o);
    int lane = tid & 31, wid = tid >> 5;
    if (lane == 0) red[wid] = v;
    __syncthreads();
    if (tid == 0) {
        float bs = 0.0f;
        #pragma unroll
        for (int w = 0; w < QBLK / 32; w++) bs += red[w];
        atomicAdd(&g_acc, bs);
        __threadfence();
        s_last = (atomicAdd(&g_done, 1) == NQBLK - 1);
    }
    __syncthreads();
    if (s_last) {
        if (tid == 0) {
            out[0] = *((volatile float*)&g_acc) * (1.0f / (2.0f * NPTS));
            g_acc = 0.0f;
            g_done = 0;
            g_ovfn[0] = 0;
            g_ovfn[1] = 0;
        }
        for (int c = tid; c < 2 * NCELL3; c += QBLK)
            ((int*)g_ccnt)[c] = 0;
    }
}

extern "C" void kernel_launch(void* const* d_in, const int* in_sizes, int n_in,
                              void* d_out, int out_size) {
    const float* a = (const float*)d_in[0];
    const float* b = (const float*)d_in[1];
    float* out = (float*)d_out;

    build_kernel<<<(2 * NPTS) / 256, 256>>>(a, b);
    query_kernel<<<NQBLK, QBLK>>>(out);
}